// round 8
// baseline (speedup 1.0000x reference)
#include <cuda_runtime.h>
#include <cuda_bf16.h>
#include <cstdint>

#define BB 8
#define LL 128
#define DD 768
#define TI 2

#define GM (BB * LL)   // 1024
#define GN DD          // 768
#define GK DD          // 768

#define AGG_BLOCKS (BB * (LL / TI))          // 512
#define WSP_BLOCKS ((GN / 64) * (GK / 64))   // 144

// ---------------- global scratch (no allocation allowed) ----------------
__device__ __nv_bfloat16 g_Ahi[GM * GK];
__device__ __nv_bfloat16 g_Alo[GM * GK];
__device__ __nv_bfloat16 g_Whi[GN * GK];   // [n][k]  (W transposed)
__device__ __nv_bfloat16 g_Wlo[GN * GK];

__device__ __forceinline__ uint32_t pack_bf16x2(float a, float b) {
    __nv_bfloat162 h = __floats2bfloat162_rn(a, b);
    return *reinterpret_cast<uint32_t*>(&h);
}

// ---------------------------------------------------------------------------
// Combined kernel 1: blocks [0,512) do agg (TI=2 i-rows each); rest do W split.
// ---------------------------------------------------------------------------
__global__ void __launch_bounds__(256, 4)
prep_kernel(const float* __restrict__ text,
            const float* __restrict__ adj,
            const float* __restrict__ dep,
            const float* __restrict__ W,
            __nv_bfloat16* __restrict__ Ahi,
            __nv_bfloat16* __restrict__ Alo,
            __nv_bfloat16* __restrict__ Whi,
            __nv_bfloat16* __restrict__ Wlo)
{
    __shared__ float sh[64 * 65];
    const int tid = threadIdx.x;

    if (blockIdx.x < AGG_BLOCKS) {
        const int b  = blockIdx.x / (LL / TI);
        const int i0 = (blockIdx.x % (LL / TI)) * TI;

        float (*s_adj)[LL] = reinterpret_cast<float (*)[LL]>(sh);
        for (int k = tid; k < TI * LL; k += 256) {
            int ii = k / LL, j = k % LL;
            s_adj[ii][j] = adj[((size_t)b * LL + (i0 + ii)) * LL + j];
        }
        __syncthreads();

        const int d0 = tid;
        float acc[TI][3];
#pragma unroll
        for (int ii = 0; ii < TI; ++ii) { acc[ii][0] = 0.f; acc[ii][1] = 0.f; acc[ii][2] = 0.f; }

        const float* textb = text + (size_t)b * LL * DD;
        const float* depb  = dep  + (size_t)b * LL * LL * DD;

#pragma unroll 2
        for (int j = 0; j < LL; ++j) {
            const float t0 = textb[(size_t)j * DD + d0];
            const float t1 = textb[(size_t)j * DD + d0 + 256];
            const float t2 = textb[(size_t)j * DD + d0 + 512];
            const float* dj = depb + (size_t)j * LL * DD + (size_t)i0 * DD + d0;
#pragma unroll
            for (int ii = 0; ii < TI; ++ii) {
                const float a = s_adj[ii][j];
                const float e0 = dj[ii * DD];
                const float e1 = dj[ii * DD + 256];
                const float e2 = dj[ii * DD + 512];
                acc[ii][0] = fmaf(a, t0 + e0, acc[ii][0]);
                acc[ii][1] = fmaf(a, t1 + e1, acc[ii][1]);
                acc[ii][2] = fmaf(a, t2 + e2, acc[ii][2]);
            }
        }

#pragma unroll
        for (int ii = 0; ii < TI; ++ii) {
#pragma unroll
            for (int p = 0; p < 3; ++p) {
                float v = acc[ii][p];
                __nv_bfloat16 h = __float2bfloat16(v);
                __nv_bfloat16 l = __float2bfloat16(v - __bfloat162float(h));
                size_t idx = ((size_t)b * LL + (i0 + ii)) * (size_t)GK + d0 + 256 * p;
                Ahi[idx] = h;
                Alo[idx] = l;
            }
        }
    } else {
        const int w  = blockIdx.x - AGG_BLOCKS;
        const int n0 = (w % (GN / 64)) * 64;
        const int k0 = (w / (GN / 64)) * 64;
        float (*t)[65] = reinterpret_cast<float (*)[65]>(sh);
        const int tx = tid & 15;
        const int ty = tid >> 4;

#pragma unroll
        for (int i = 0; i < 4; ++i) {
            const int row = ty + 16 * i;
            const float4 v = *reinterpret_cast<const float4*>(
                &W[(size_t)(k0 + row) * GN + n0 + tx * 4]);
            t[row][tx * 4 + 0] = v.x;
            t[row][tx * 4 + 1] = v.y;
            t[row][tx * 4 + 2] = v.z;
            t[row][tx * 4 + 3] = v.w;
        }
        __syncthreads();

#pragma unroll
        for (int i = 0; i < 4; ++i) {
            const int n = ty + 16 * i;
            const int k = tx * 4;
            const float v0 = t[k + 0][n];
            const float v1 = t[k + 1][n];
            const float v2 = t[k + 2][n];
            const float v3 = t[k + 3][n];
            const float h0 = __bfloat162float(__float2bfloat16(v0));
            const float h1 = __bfloat162float(__float2bfloat16(v1));
            const float h2 = __bfloat162float(__float2bfloat16(v2));
            const float h3 = __bfloat162float(__float2bfloat16(v3));
            uint2 hi, lo;
            hi.x = pack_bf16x2(v0, v1);
            hi.y = pack_bf16x2(v2, v3);
            lo.x = pack_bf16x2(v0 - h0, v1 - h1);
            lo.y = pack_bf16x2(v2 - h2, v3 - h3);
            const size_t idx = (size_t)(n0 + n) * GK + k0 + k;
            *reinterpret_cast<uint2*>(Whi + idx) = hi;
            *reinterpret_cast<uint2*>(Wlo + idx) = lo;
        }
    }
}

// ---------------------------------------------------------------------------
// Kernel 2: HMMA bf16 GEMM, hi/lo 3-pass, fp32 accum.  (R6-proven config)
// 64x96 CTA tile -> 128 CTAs (one wave), BK=64, 2-stage cp.async,
// 8 warps: warp tile 32x24.
// ---------------------------------------------------------------------------
#define BM 64
#define BN 96
#define BK 64
#define NCH (GK / BK)            // 12
#define PITCH 144
#define A_TILE_B (BM * PITCH)    // 9216
#define B_TILE_B (BN * PITCH)    // 13824
#define STAGE_B (2 * A_TILE_B + 2 * B_TILE_B)   // 46080
#define GEMM_SMEM (2 * STAGE_B)                 // 92160

__device__ __forceinline__ uint32_t smem_u32(const void* p) {
    uint32_t a;
    asm("{ .reg .u64 t; cvta.to.shared.u64 t, %1; cvt.u32.u64 %0, t; }" : "=r"(a) : "l"(p));
    return a;
}
__device__ __forceinline__ void cp_async16(uint32_t dst, const void* src) {
    asm volatile("cp.async.cg.shared.global [%0], [%1], 16;" :: "r"(dst), "l"(src));
}
#define CP_COMMIT() asm volatile("cp.async.commit_group;")
#define CP_WAIT1()  asm volatile("cp.async.wait_group 1;")

__device__ __forceinline__ void ldsm_x4(uint32_t* r, uint32_t addr) {
    asm volatile("ldmatrix.sync.aligned.m8n8.x4.shared.b16 {%0,%1,%2,%3}, [%4];"
                 : "=r"(r[0]), "=r"(r[1]), "=r"(r[2]), "=r"(r[3]) : "r"(addr));
}
__device__ __forceinline__ void ldsm_x2(uint32_t* r, uint32_t addr) {
    asm volatile("ldmatrix.sync.aligned.m8n8.x2.shared.b16 {%0,%1}, [%2];"
                 : "=r"(r[0]), "=r"(r[1]) : "r"(addr));
}
__device__ __forceinline__ void mma_bf16(float* c, const uint32_t* a, const uint32_t* b) {
    asm volatile(
        "mma.sync.aligned.m16n8k16.row.col.f32.bf16.bf16.f32 "
        "{%0,%1,%2,%3}, {%4,%5,%6,%7}, {%8,%9}, {%0,%1,%2,%3};"
        : "+f"(c[0]), "+f"(c[1]), "+f"(c[2]), "+f"(c[3])
        : "r"(a[0]), "r"(a[1]), "r"(a[2]), "r"(a[3]), "r"(b[0]), "r"(b[1]));
}

__global__ void __launch_bounds__(256, 1)
gemm_hmma(const __nv_bfloat16* __restrict__ Ahi,
          const __nv_bfloat16* __restrict__ Alo,
          const __nv_bfloat16* __restrict__ Whi,
          const __nv_bfloat16* __restrict__ Wlo,
          const float* __restrict__ bias,
          float* __restrict__ out)
{
    extern __shared__ char smem[];
    const uint32_t sbase = smem_u32(smem);
    const int tid = threadIdx.x;
    const int wid = tid >> 5;
    const int lid = tid & 31;

    const int n0 = blockIdx.x * BN;
    const int m0 = blockIdx.y * BM;
    const int warp_m = wid >> 2;     // 0..1
    const int warp_n = wid & 3;      // 0..3

    const int l_row = tid >> 3;      // 0..31
    const int l_c16 = tid & 7;

    float acc[2][3][4];
#pragma unroll
    for (int mt = 0; mt < 2; ++mt)
#pragma unroll
        for (int nt = 0; nt < 3; ++nt)
#pragma unroll
            for (int r = 0; r < 4; ++r) acc[mt][nt][r] = 0.f;

    auto load_chunk = [&](int c, int s) {
        const int k0 = c * BK;
        const uint32_t stage = sbase + s * STAGE_B;
        const uint32_t tAhi = stage;
        const uint32_t tAlo = stage + A_TILE_B;
        const uint32_t tBhi = stage + 2 * A_TILE_B;
        const uint32_t tBlo = stage + 2 * A_TILE_B + B_TILE_B;
#pragma unroll
        for (int i = 0; i < 2; ++i) {
            const int row = l_row + 32 * i;
            const uint32_t doff = (uint32_t)(row * PITCH + l_c16 * 16);
            const size_t ga = (size_t)(m0 + row) * GK + k0 + l_c16 * 8;
            cp_async16(tAhi + doff, Ahi + ga);
            cp_async16(tAlo + doff, Alo + ga);
        }
#pragma unroll
        for (int i = 0; i < 3; ++i) {
            const int row = l_row + 32 * i;
            const uint32_t doff = (uint32_t)(row * PITCH + l_c16 * 16);
            const size_t gb = (size_t)(n0 + row) * GK + k0 + l_c16 * 8;
            cp_async16(tBhi + doff, Whi + gb);
            cp_async16(tBlo + doff, Wlo + gb);
        }
    };

    load_chunk(0, 0); CP_COMMIT();
    load_chunk(1, 1); CP_COMMIT();

    const int a_sub = lid >> 3;
    const int a_row_off = (a_sub & 1) * 8 + (lid & 7);
    const int a_col_off = (a_sub >> 1) * 16;
    const int b_sub = lid >> 3;
    const int b_row_off = (b_sub >> 1) * 8 + (lid & 7);
    const int b_col_off = (b_sub & 1) * 16;
    const int b2_row_off = 16 + (lid & 7);
    const int b2_col_off = ((lid >> 3) & 1) * 16;

    for (int c = 0; c < NCH; ++c) {
        CP_WAIT1();
        __syncthreads();

        const uint32_t stage = sbase + (c & 1) * STAGE_B;
        const uint32_t tAhi = stage;
        const uint32_t tAlo = stage + A_TILE_B;
        const uint32_t tBhi = stage + 2 * A_TILE_B;
        const uint32_t tBlo = stage + 2 * A_TILE_B + B_TILE_B;

#pragma unroll
        for (int ks = 0; ks < BK / 16; ++ks) {
            const int kb = ks * 32;
            uint32_t ah[2][4], al[2][4], bh[6], bl[6];
#pragma unroll
            for (int mt = 0; mt < 2; ++mt) {
                const uint32_t ao =
                    (uint32_t)((warp_m * 32 + mt * 16 + a_row_off) * PITCH + kb + a_col_off);
                ldsm_x4(ah[mt], tAhi + ao);
                ldsm_x4(al[mt], tAlo + ao);
            }
            {
                const uint32_t bo =
                    (uint32_t)((warp_n * 24 + b_row_off) * PITCH + kb + b_col_off);
                ldsm_x4(bh, tBhi + bo);
                ldsm_x4(bl, tBlo + bo);
                const uint32_t bo2 =
                    (uint32_t)((warp_n * 24 + b2_row_off) * PITCH + kb + b2_col_off);
                ldsm_x2(bh + 4, tBhi + bo2);
                ldsm_x2(bl + 4, tBlo + bo2);
            }
#pragma unroll
            for (int mt = 0; mt < 2; ++mt)
#pragma unroll
                for (int nt = 0; nt < 3; ++nt) {
                    const uint32_t* bhf = &bh[nt * 2];
                    const uint32_t* blf = &bl[nt * 2];
                    mma_bf16(acc[mt][nt], ah[mt], bhf);
                    mma_bf16(acc[mt][nt], ah[mt], blf);
                    mma_bf16(acc[mt][nt], al[mt], bhf);
                }
        }
        __syncthreads();

        if (c + 2 < NCH) load_chunk(c + 2, c & 1);
        CP_COMMIT();
    }

    // ---- epilogue: bias + relu ----
    const int col_base = n0 + warp_n * 24 + 2 * (lid & 3);
    const int row_base = m0 + warp_m * 32 + (lid >> 2);
#pragma unroll
    for (int mt = 0; mt < 2; ++mt) {
#pragma unroll
        for (int nt = 0; nt < 3; ++nt) {
            const int col = col_base + nt * 8;
            const float2 bv = *reinterpret_cast<const float2*>(&bias[col]);
#pragma unroll
            for (int h = 0; h < 2; ++h) {
                const int row = row_base + mt * 16 + h * 8;
                float2 o;
                o.x = fmaxf(acc[mt][nt][2 * h + 0] + bv.x, 0.f);
                o.y = fmaxf(acc[mt][nt][2 * h + 1] + bv.y, 0.f);
                *reinterpret_cast<float2*>(&out[(size_t)row * GN + col]) = o;
            }
        }
    }
}

// ---------------------------------------------------------------------------
extern "C" void kernel_launch(void* const* d_in, const int* in_sizes, int n_in,
                              void* d_out, int out_size)
{
    const float* text = (const float*)d_in[0];
    const float* adj  = (const float*)d_in[1];
    const float* dep  = (const float*)d_in[2];
    const float* W    = (const float*)d_in[3];
    const float* bias = (const float*)d_in[4];
    float* out = (float*)d_out;

    __nv_bfloat16 *Ahi, *Alo, *Whi, *Wlo;
    cudaGetSymbolAddress((void**)&Ahi, g_Ahi);
    cudaGetSymbolAddress((void**)&Alo, g_Alo);
    cudaGetSymbolAddress((void**)&Whi, g_Whi);
    cudaGetSymbolAddress((void**)&Wlo, g_Wlo);

    cudaFuncSetAttribute(gemm_hmma, cudaFuncAttributeMaxDynamicSharedMemorySize, GEMM_SMEM);

    prep_kernel<<<AGG_BLOCKS + WSP_BLOCKS, 256>>>(text, adj, dep, W, Ahi, Alo, Whi, Wlo);
    gemm_hmma<<<dim3(GN / BN, GM / BM), 256, GEMM_SMEM>>>(Ahi, Alo, Whi, Wlo, bias, out);
}

// round 9
// speedup vs baseline: 1.0652x; 1.0652x over previous
#include <cuda_runtime.h>
#include <cuda_bf16.h>
#include <cstdint>

#define BB 8
#define LL 128
#define DD 768
#define TI 4

#define GM (BB * LL)   // 1024
#define GN DD          // 768
#define GK DD          // 768

#define AGG_BLOCKS (BB * (LL / TI))          // 256
#define WSP_BLOCKS ((GN / 64) * (GK / 64))   // 144

// ---------------- global scratch (no allocation allowed) ----------------
__device__ __nv_bfloat16 g_Ahi[GM * GK];
__device__ __nv_bfloat16 g_Alo[GM * GK];
__device__ __nv_bfloat16 g_Whi[GN * GK];   // [n][k]  (W transposed)
__device__ __nv_bfloat16 g_Wlo[GN * GK];

__device__ __forceinline__ uint32_t pack_bf16x2(float a, float b) {
    __nv_bfloat162 h = __floats2bfloat162_rn(a, b);
    return *reinterpret_cast<uint32_t*>(&h);
}

// ---------------------------------------------------------------------------
// Combined kernel 1: blocks [0,256) do agg; blocks [256,400) do W split.
// (R3/R6-proven body — frozen)
// ---------------------------------------------------------------------------
__global__ void __launch_bounds__(256, 4)
prep_kernel(const float* __restrict__ text,
            const float* __restrict__ adj,
            const float* __restrict__ dep,
            const float* __restrict__ W,
            __nv_bfloat16* __restrict__ Ahi,
            __nv_bfloat16* __restrict__ Alo,
            __nv_bfloat16* __restrict__ Whi,
            __nv_bfloat16* __restrict__ Wlo)
{
    __shared__ float sh[64 * 65];
    const int tid = threadIdx.x;

    if (blockIdx.x < AGG_BLOCKS) {
        const int b  = blockIdx.x / (LL / TI);
        const int i0 = (blockIdx.x % (LL / TI)) * TI;

        float (*s_adj)[LL] = reinterpret_cast<float (*)[LL]>(sh);
        for (int k = tid; k < TI * LL; k += 256) {
            int ii = k / LL, j = k % LL;
            s_adj[ii][j] = adj[((size_t)b * LL + (i0 + ii)) * LL + j];
        }
        __syncthreads();

        const int d0 = tid;
        float acc[TI][3];
#pragma unroll
        for (int ii = 0; ii < TI; ++ii) { acc[ii][0] = 0.f; acc[ii][1] = 0.f; acc[ii][2] = 0.f; }

        const float* textb = text + (size_t)b * LL * DD;
        const float* depb  = dep  + (size_t)b * LL * LL * DD;

#pragma unroll 2
        for (int j = 0; j < LL; ++j) {
            const float t0 = textb[(size_t)j * DD + d0];
            const float t1 = textb[(size_t)j * DD + d0 + 256];
            const float t2 = textb[(size_t)j * DD + d0 + 512];
            const float* dj = depb + (size_t)j * LL * DD + (size_t)i0 * DD + d0;
#pragma unroll
            for (int ii = 0; ii < TI; ++ii) {
                const float a = s_adj[ii][j];
                const float e0 = dj[ii * DD];
                const float e1 = dj[ii * DD + 256];
                const float e2 = dj[ii * DD + 512];
                acc[ii][0] = fmaf(a, t0 + e0, acc[ii][0]);
                acc[ii][1] = fmaf(a, t1 + e1, acc[ii][1]);
                acc[ii][2] = fmaf(a, t2 + e2, acc[ii][2]);
            }
        }

#pragma unroll
        for (int ii = 0; ii < TI; ++ii) {
#pragma unroll
            for (int p = 0; p < 3; ++p) {
                float v = acc[ii][p];
                __nv_bfloat16 h = __float2bfloat16(v);
                __nv_bfloat16 l = __float2bfloat16(v - __bfloat162float(h));
                size_t idx = ((size_t)b * LL + (i0 + ii)) * (size_t)GK + d0 + 256 * p;
                Ahi[idx] = h;
                Alo[idx] = l;
            }
        }
    } else {
        const int w  = blockIdx.x - AGG_BLOCKS;
        const int n0 = (w % (GN / 64)) * 64;
        const int k0 = (w / (GN / 64)) * 64;
        float (*t)[65] = reinterpret_cast<float (*)[65]>(sh);
        const int tx = tid & 15;
        const int ty = tid >> 4;

#pragma unroll
        for (int i = 0; i < 4; ++i) {
            const int row = ty + 16 * i;
            const float4 v = *reinterpret_cast<const float4*>(
                &W[(size_t)(k0 + row) * GN + n0 + tx * 4]);
            t[row][tx * 4 + 0] = v.x;
            t[row][tx * 4 + 1] = v.y;
            t[row][tx * 4 + 2] = v.z;
            t[row][tx * 4 + 3] = v.w;
        }
        __syncthreads();

#pragma unroll
        for (int i = 0; i < 4; ++i) {
            const int n = ty + 16 * i;
            const int k = tx * 4;
            const float v0 = t[k + 0][n];
            const float v1 = t[k + 1][n];
            const float v2 = t[k + 2][n];
            const float v3 = t[k + 3][n];
            const float h0 = __bfloat162float(__float2bfloat16(v0));
            const float h1 = __bfloat162float(__float2bfloat16(v1));
            const float h2 = __bfloat162float(__float2bfloat16(v2));
            const float h3 = __bfloat162float(__float2bfloat16(v3));
            uint2 hi, lo;
            hi.x = pack_bf16x2(v0, v1);
            hi.y = pack_bf16x2(v2, v3);
            lo.x = pack_bf16x2(v0 - h0, v1 - h1);
            lo.y = pack_bf16x2(v2 - h2, v3 - h3);
            const size_t idx = (size_t)(n0 + n) * GK + k0 + k;
            *reinterpret_cast<uint2*>(Whi + idx) = hi;
            *reinterpret_cast<uint2*>(Wlo + idx) = lo;
        }
    }
}

// ---------------------------------------------------------------------------
// Kernel 2: HMMA bf16 GEMM, hi/lo 3-pass, fp32 accum.
// 64x96 CTA tile -> 128 CTAs (one wave), BK=64, **3-stage** cp.async ring,
// 8 warps: warp tile 32x24.
// ---------------------------------------------------------------------------
#define BM 64
#define BN 96
#define BK 64
#define NCH (GK / BK)            // 12
#define NSTAGE 3
#define PITCH 144
#define A_TILE_B (BM * PITCH)    // 9216
#define B_TILE_B (BN * PITCH)    // 13824
#define STAGE_B (2 * A_TILE_B + 2 * B_TILE_B)   // 46080
#define GEMM_SMEM (NSTAGE * STAGE_B)            // 138240

__device__ __forceinline__ uint32_t smem_u32(const void* p) {
    uint32_t a;
    asm("{ .reg .u64 t; cvta.to.shared.u64 t, %1; cvt.u32.u64 %0, t; }" : "=r"(a) : "l"(p));
    return a;
}
__device__ __forceinline__ void cp_async16(uint32_t dst, const void* src) {
    asm volatile("cp.async.cg.shared.global [%0], [%1], 16;" :: "r"(dst), "l"(src));
}
#define CP_COMMIT() asm volatile("cp.async.commit_group;")
#define CP_WAIT2()  asm volatile("cp.async.wait_group 2;")

__device__ __forceinline__ void ldsm_x4(uint32_t* r, uint32_t addr) {
    asm volatile("ldmatrix.sync.aligned.m8n8.x4.shared.b16 {%0,%1,%2,%3}, [%4];"
                 : "=r"(r[0]), "=r"(r[1]), "=r"(r[2]), "=r"(r[3]) : "r"(addr));
}
__device__ __forceinline__ void ldsm_x2(uint32_t* r, uint32_t addr) {
    asm volatile("ldmatrix.sync.aligned.m8n8.x2.shared.b16 {%0,%1}, [%2];"
                 : "=r"(r[0]), "=r"(r[1]) : "r"(addr));
}
__device__ __forceinline__ void mma_bf16(float* c, const uint32_t* a, const uint32_t* b) {
    asm volatile(
        "mma.sync.aligned.m16n8k16.row.col.f32.bf16.bf16.f32 "
        "{%0,%1,%2,%3}, {%4,%5,%6,%7}, {%8,%9}, {%0,%1,%2,%3};"
        : "+f"(c[0]), "+f"(c[1]), "+f"(c[2]), "+f"(c[3])
        : "r"(a[0]), "r"(a[1]), "r"(a[2]), "r"(a[3]), "r"(b[0]), "r"(b[1]));
}

__global__ void __launch_bounds__(256, 1)
gemm_hmma(const __nv_bfloat16* __restrict__ Ahi,
          const __nv_bfloat16* __restrict__ Alo,
          const __nv_bfloat16* __restrict__ Whi,
          const __nv_bfloat16* __restrict__ Wlo,
          const float* __restrict__ bias,
          float* __restrict__ out)
{
    extern __shared__ char smem[];
    const uint32_t sbase = smem_u32(smem);
    const int tid = threadIdx.x;
    const int wid = tid >> 5;
    const int lid = tid & 31;

    const int n0 = blockIdx.x * BN;
    const int m0 = blockIdx.y * BM;
    const int warp_m = wid >> 2;     // 0..1
    const int warp_n = wid & 3;      // 0..3

    const int l_row = tid >> 3;      // 0..31
    const int l_c16 = tid & 7;

    float acc[2][3][4];
#pragma unroll
    for (int mt = 0; mt < 2; ++mt)
#pragma unroll
        for (int nt = 0; nt < 3; ++nt)
#pragma unroll
            for (int r = 0; r < 4; ++r) acc[mt][nt][r] = 0.f;

    auto load_chunk = [&](int c, int s) {
        const int k0 = c * BK;
        const uint32_t stage = sbase + s * STAGE_B;
        const uint32_t tAhi = stage;
        const uint32_t tAlo = stage + A_TILE_B;
        const uint32_t tBhi = stage + 2 * A_TILE_B;
        const uint32_t tBlo = stage + 2 * A_TILE_B + B_TILE_B;
#pragma unroll
        for (int i = 0; i < 2; ++i) {
            const int row = l_row + 32 * i;
            const uint32_t doff = (uint32_t)(row * PITCH + l_c16 * 16);
            const size_t ga = (size_t)(m0 + row) * GK + k0 + l_c16 * 8;
            cp_async16(tAhi + doff, Ahi + ga);
            cp_async16(tAlo + doff, Alo + ga);
        }
#pragma unroll
        for (int i = 0; i < 3; ++i) {
            const int row = l_row + 32 * i;
            const uint32_t doff = (uint32_t)(row * PITCH + l_c16 * 16);
            const size_t gb = (size_t)(n0 + row) * GK + k0 + l_c16 * 8;
            cp_async16(tBhi + doff, Whi + gb);
            cp_async16(tBlo + doff, Wlo + gb);
        }
    };

    load_chunk(0, 0); CP_COMMIT();
    load_chunk(1, 1); CP_COMMIT();
    load_chunk(2, 2); CP_COMMIT();

    const int a_sub = lid >> 3;
    const int a_row_off = (a_sub & 1) * 8 + (lid & 7);
    const int a_col_off = (a_sub >> 1) * 16;
    const int b_sub = lid >> 3;
    const int b_row_off = (b_sub >> 1) * 8 + (lid & 7);
    const int b_col_off = (b_sub & 1) * 16;
    const int b2_row_off = 16 + (lid & 7);
    const int b2_col_off = ((lid >> 3) & 1) * 16;

    int stage_idx = 0;
    for (int c = 0; c < NCH; ++c) {
        CP_WAIT2();          // chunk c arrived (c+1, c+2 may still be in flight)
        __syncthreads();

        const uint32_t stage = sbase + stage_idx * STAGE_B;
        const uint32_t tAhi = stage;
        const uint32_t tAlo = stage + A_TILE_B;
        const uint32_t tBhi = stage + 2 * A_TILE_B;
        const uint32_t tBlo = stage + 2 * A_TILE_B + B_TILE_B;

#pragma unroll
        for (int ks = 0; ks < BK / 16; ++ks) {
            const int kb = ks * 32;
            uint32_t ah[2][4], al[2][4], bh[6], bl[6];
#pragma unroll
            for (int mt = 0; mt < 2; ++mt) {
                const uint32_t ao =
                    (uint32_t)((warp_m * 32 + mt * 16 + a_row_off) * PITCH + kb + a_col_off);
                ldsm_x4(ah[mt], tAhi + ao);
                ldsm_x4(al[mt], tAlo + ao);
            }
            {
                const uint32_t bo =
                    (uint32_t)((warp_n * 24 + b_row_off) * PITCH + kb + b_col_off);
                ldsm_x4(bh, tBhi + bo);
                ldsm_x4(bl, tBlo + bo);
                const uint32_t bo2 =
                    (uint32_t)((warp_n * 24 + b2_row_off) * PITCH + kb + b2_col_off);
                ldsm_x2(bh + 4, tBhi + bo2);
                ldsm_x2(bl + 4, tBlo + bo2);
            }
#pragma unroll
            for (int mt = 0; mt < 2; ++mt)
#pragma unroll
                for (int nt = 0; nt < 3; ++nt) {
                    const uint32_t* bhf = &bh[nt * 2];
                    const uint32_t* blf = &bl[nt * 2];
                    mma_bf16(acc[mt][nt], ah[mt], bhf);
                    mma_bf16(acc[mt][nt], ah[mt], blf);
                    mma_bf16(acc[mt][nt], al[mt], bhf);
                }
        }
        __syncthreads();     // stage_idx buffer free for reuse

        if (c + NSTAGE < NCH) load_chunk(c + NSTAGE, stage_idx);
        CP_COMMIT();
        stage_idx = (stage_idx + 1 == NSTAGE) ? 0 : stage_idx + 1;
    }

    // ---- epilogue: bias + relu ----
    const int col_base = n0 + warp_n * 24 + 2 * (lid & 3);
    const int row_base = m0 + warp_m * 32 + (lid >> 2);
#pragma unroll
    for (int mt = 0; mt < 2; ++mt) {
#pragma unroll
        for (int nt = 0; nt < 3; ++nt) {
            const int col = col_base + nt * 8;
            const float2 bv = *reinterpret_cast<const float2*>(&bias[col]);
#pragma unroll
            for (int h = 0; h < 2; ++h) {
                const int row = row_base + mt * 16 + h * 8;
                float2 o;
                o.x = fmaxf(acc[mt][nt][2 * h + 0] + bv.x, 0.f);
                o.y = fmaxf(acc[mt][nt][2 * h + 1] + bv.y, 0.f);
                *reinterpret_cast<float2*>(&out[(size_t)row * GN + col]) = o;
            }
        }
    }
}

// ---------------------------------------------------------------------------
extern "C" void kernel_launch(void* const* d_in, const int* in_sizes, int n_in,
                              void* d_out, int out_size)
{
    const float* text = (const float*)d_in[0];
    const float* adj  = (const float*)d_in[1];
    const float* dep  = (const float*)d_in[2];
    const float* W    = (const float*)d_in[3];
    const float* bias = (const float*)d_in[4];
    float* out = (float*)d_out;

    __nv_bfloat16 *Ahi, *Alo, *Whi, *Wlo;
    cudaGetSymbolAddress((void**)&Ahi, g_Ahi);
    cudaGetSymbolAddress((void**)&Alo, g_Alo);
    cudaGetSymbolAddress((void**)&Whi, g_Whi);
    cudaGetSymbolAddress((void**)&Wlo, g_Wlo);

    cudaFuncSetAttribute(gemm_hmma, cudaFuncAttributeMaxDynamicSharedMemorySize, GEMM_SMEM);

    prep_kernel<<<AGG_BLOCKS + WSP_BLOCKS, 256>>>(text, adj, dep, W, Ahi, Alo, Whi, Wlo);
    gemm_hmma<<<dim3(GN / BN, GM / BM), 256, GEMM_SMEM>>>(Ahi, Alo, Whi, Wlo, bias, out);
}

// round 10
// speedup vs baseline: 1.1179x; 1.0495x over previous
#include <cuda_runtime.h>
#include <cuda_fp16.h>
#include <cstdint>

#define BB 8
#define LL 128
#define DD 768
#define TI 4

#define GM (BB * LL)   // 1024
#define GN DD          // 768
#define GK DD          // 768

#define AGG_BLOCKS (BB * (LL / TI))          // 256
#define WSP_BLOCKS ((GN / 64) * (GK / 64))   // 144

// ---------------- global scratch (no allocation allowed) ----------------
__device__ __half g_Ahi[GM * GK];
__device__ __half g_Whi[GN * GK];   // [n][k]  (W transposed)
__device__ __half g_Wlo[GN * GK];

__device__ __forceinline__ uint32_t pack_h2(float a, float b) {
    __half2 h = __floats2half2_rn(a, b);
    return *reinterpret_cast<uint32_t*>(&h);
}

// ---------------------------------------------------------------------------
// Combined kernel 1: blocks [0,256) do agg; blocks [256,400) do W split.
// agg emits fp16 (hi only); W split emits fp16 hi/lo.
// ---------------------------------------------------------------------------
__global__ void __launch_bounds__(256, 4)
prep_kernel(const float* __restrict__ text,
            const float* __restrict__ adj,
            const float* __restrict__ dep,
            const float* __restrict__ W,
            __half* __restrict__ Ahi,
            __half* __restrict__ Whi,
            __half* __restrict__ Wlo)
{
    __shared__ float sh[64 * 65];
    const int tid = threadIdx.x;

    if (blockIdx.x < AGG_BLOCKS) {
        const int b  = blockIdx.x / (LL / TI);
        const int i0 = (blockIdx.x % (LL / TI)) * TI;

        float (*s_adj)[LL] = reinterpret_cast<float (*)[LL]>(sh);
        for (int k = tid; k < TI * LL; k += 256) {
            int ii = k / LL, j = k % LL;
            s_adj[ii][j] = adj[((size_t)b * LL + (i0 + ii)) * LL + j];
        }
        __syncthreads();

        const int d0 = tid;
        float acc[TI][3];
#pragma unroll
        for (int ii = 0; ii < TI; ++ii) { acc[ii][0] = 0.f; acc[ii][1] = 0.f; acc[ii][2] = 0.f; }

        const float* textb = text + (size_t)b * LL * DD;
        const float* depb  = dep  + (size_t)b * LL * LL * DD;

#pragma unroll 2
        for (int j = 0; j < LL; ++j) {
            const float t0 = textb[(size_t)j * DD + d0];
            const float t1 = textb[(size_t)j * DD + d0 + 256];
            const float t2 = textb[(size_t)j * DD + d0 + 512];
            const float* dj = depb + (size_t)j * LL * DD + (size_t)i0 * DD + d0;
#pragma unroll
            for (int ii = 0; ii < TI; ++ii) {
                const float a = s_adj[ii][j];
                const float e0 = dj[ii * DD];
                const float e1 = dj[ii * DD + 256];
                const float e2 = dj[ii * DD + 512];
                acc[ii][0] = fmaf(a, t0 + e0, acc[ii][0]);
                acc[ii][1] = fmaf(a, t1 + e1, acc[ii][1]);
                acc[ii][2] = fmaf(a, t2 + e2, acc[ii][2]);
            }
        }

#pragma unroll
        for (int ii = 0; ii < TI; ++ii) {
#pragma unroll
            for (int p = 0; p < 3; ++p) {
                size_t idx = ((size_t)b * LL + (i0 + ii)) * (size_t)GK + d0 + 256 * p;
                Ahi[idx] = __float2half(acc[ii][p]);
            }
        }
    } else {
        const int w  = blockIdx.x - AGG_BLOCKS;
        const int n0 = (w % (GN / 64)) * 64;
        const int k0 = (w / (GN / 64)) * 64;
        float (*t)[65] = reinterpret_cast<float (*)[65]>(sh);
        const int tx = tid & 15;
        const int ty = tid >> 4;

#pragma unroll
        for (int i = 0; i < 4; ++i) {
            const int row = ty + 16 * i;
            const float4 v = *reinterpret_cast<const float4*>(
                &W[(size_t)(k0 + row) * GN + n0 + tx * 4]);
            t[row][tx * 4 + 0] = v.x;
            t[row][tx * 4 + 1] = v.y;
            t[row][tx * 4 + 2] = v.z;
            t[row][tx * 4 + 3] = v.w;
        }
        __syncthreads();

#pragma unroll
        for (int i = 0; i < 4; ++i) {
            const int n = ty + 16 * i;
            const int k = tx * 4;
            const float v0 = t[k + 0][n];
            const float v1 = t[k + 1][n];
            const float v2 = t[k + 2][n];
            const float v3 = t[k + 3][n];
            const float h0 = __half2float(__float2half(v0));
            const float h1 = __half2float(__float2half(v1));
            const float h2 = __half2float(__float2half(v2));
            const float h3 = __half2float(__float2half(v3));
            uint2 hi, lo;
            hi.x = pack_h2(v0, v1);
            hi.y = pack_h2(v2, v3);
            lo.x = pack_h2(v0 - h0, v1 - h1);
            lo.y = pack_h2(v2 - h2, v3 - h3);
            const size_t idx = (size_t)(n0 + n) * GK + k0 + k;
            *reinterpret_cast<uint2*>(Whi + idx) = hi;
            *reinterpret_cast<uint2*>(Wlo + idx) = lo;
        }
    }
}

// ---------------------------------------------------------------------------
// Kernel 2: HMMA fp16 GEMM, 2-pass (Ahi*Whi + Ahi*Wlo), fp32 accum.
// 64x96 CTA tile -> 128 CTAs (one wave), BK=64, 3-stage cp.async ring,
// 8 warps: warp tile 32x24.
// ---------------------------------------------------------------------------
#define BM 64
#define BN 96
#define BK 64
#define NCH (GK / BK)            // 12
#define NSTAGE 3
#define PITCH 144
#define A_TILE_B (BM * PITCH)    // 9216
#define B_TILE_B (BN * PITCH)    // 13824
#define STAGE_B (A_TILE_B + 2 * B_TILE_B)   // 36864
#define GEMM_SMEM (NSTAGE * STAGE_B)        // 110592

__device__ __forceinline__ uint32_t smem_u32(const void* p) {
    uint32_t a;
    asm("{ .reg .u64 t; cvta.to.shared.u64 t, %1; cvt.u32.u64 %0, t; }" : "=r"(a) : "l"(p));
    return a;
}
__device__ __forceinline__ void cp_async16(uint32_t dst, const void* src) {
    asm volatile("cp.async.cg.shared.global [%0], [%1], 16;" :: "r"(dst), "l"(src));
}
#define CP_COMMIT() asm volatile("cp.async.commit_group;")
#define CP_WAIT2()  asm volatile("cp.async.wait_group 2;")

__device__ __forceinline__ void ldsm_x4(uint32_t* r, uint32_t addr) {
    asm volatile("ldmatrix.sync.aligned.m8n8.x4.shared.b16 {%0,%1,%2,%3}, [%4];"
                 : "=r"(r[0]), "=r"(r[1]), "=r"(r[2]), "=r"(r[3]) : "r"(addr));
}
__device__ __forceinline__ void ldsm_x2(uint32_t* r, uint32_t addr) {
    asm volatile("ldmatrix.sync.aligned.m8n8.x2.shared.b16 {%0,%1}, [%2];"
                 : "=r"(r[0]), "=r"(r[1]) : "r"(addr));
}
__device__ __forceinline__ void mma_f16(float* c, const uint32_t* a, const uint32_t* b) {
    asm volatile(
        "mma.sync.aligned.m16n8k16.row.col.f32.f16.f16.f32 "
        "{%0,%1,%2,%3}, {%4,%5,%6,%7}, {%8,%9}, {%0,%1,%2,%3};"
        : "+f"(c[0]), "+f"(c[1]), "+f"(c[2]), "+f"(c[3])
        : "r"(a[0]), "r"(a[1]), "r"(a[2]), "r"(a[3]), "r"(b[0]), "r"(b[1]));
}

__global__ void __launch_bounds__(256, 1)
gemm_hmma(const __half* __restrict__ Ahi,
          const __half* __restrict__ Whi,
          const __half* __restrict__ Wlo,
          const float* __restrict__ bias,
          float* __restrict__ out)
{
    extern __shared__ char smem[];
    const uint32_t sbase = smem_u32(smem);
    const int tid = threadIdx.x;
    const int wid = tid >> 5;
    const int lid = tid & 31;

    const int n0 = blockIdx.x * BN;
    const int m0 = blockIdx.y * BM;
    const int warp_m = wid >> 2;     // 0..1
    const int warp_n = wid & 3;      // 0..3

    const int l_row = tid >> 3;      // 0..31
    const int l_c16 = tid & 7;

    float acc[2][3][4];
#pragma unroll
    for (int mt = 0; mt < 2; ++mt)
#pragma unroll
        for (int nt = 0; nt < 3; ++nt)
#pragma unroll
            for (int r = 0; r < 4; ++r) acc[mt][nt][r] = 0.f;

    auto load_chunk = [&](int c, int s) {
        const int k0 = c * BK;
        const uint32_t stage = sbase + s * STAGE_B;
        const uint32_t tAhi = stage;
        const uint32_t tBhi = stage + A_TILE_B;
        const uint32_t tBlo = stage + A_TILE_B + B_TILE_B;
#pragma unroll
        for (int i = 0; i < 2; ++i) {
            const int row = l_row + 32 * i;
            const uint32_t doff = (uint32_t)(row * PITCH + l_c16 * 16);
            const size_t ga = (size_t)(m0 + row) * GK + k0 + l_c16 * 8;
            cp_async16(tAhi + doff, Ahi + ga);
        }
#pragma unroll
        for (int i = 0; i < 3; ++i) {
            const int row = l_row + 32 * i;
            const uint32_t doff = (uint32_t)(row * PITCH + l_c16 * 16);
            const size_t gb = (size_t)(n0 + row) * GK + k0 + l_c16 * 8;
            cp_async16(tBhi + doff, Whi + gb);
            cp_async16(tBlo + doff, Wlo + gb);
        }
    };

    load_chunk(0, 0); CP_COMMIT();
    load_chunk(1, 1); CP_COMMIT();
    load_chunk(2, 2); CP_COMMIT();

    const int a_sub = lid >> 3;
    const int a_row_off = (a_sub & 1) * 8 + (lid & 7);
    const int a_col_off = (a_sub >> 1) * 16;
    const int b_sub = lid >> 3;
    const int b_row_off = (b_sub >> 1) * 8 + (lid & 7);
    const int b_col_off = (b_sub & 1) * 16;
    const int b2_row_off = 16 + (lid & 7);
    const int b2_col_off = ((lid >> 3) & 1) * 16;

    int stage_idx = 0;
    for (int c = 0; c < NCH; ++c) {
        CP_WAIT2();
        __syncthreads();

        const uint32_t stage = sbase + stage_idx * STAGE_B;
        const uint32_t tAhi = stage;
        const uint32_t tBhi = stage + A_TILE_B;
        const uint32_t tBlo = stage + A_TILE_B + B_TILE_B;

#pragma unroll
        for (int ks = 0; ks < BK / 16; ++ks) {
            const int kb = ks * 32;
            uint32_t ah[2][4], bh[6], bl[6];
#pragma unroll
            for (int mt = 0; mt < 2; ++mt) {
                const uint32_t ao =
                    (uint32_t)((warp_m * 32 + mt * 16 + a_row_off) * PITCH + kb + a_col_off);
                ldsm_x4(ah[mt], tAhi + ao);
            }
            {
                const uint32_t bo =
                    (uint32_t)((warp_n * 24 + b_row_off) * PITCH + kb + b_col_off);
                ldsm_x4(bh, tBhi + bo);
                ldsm_x4(bl, tBlo + bo);
                const uint32_t bo2 =
                    (uint32_t)((warp_n * 24 + b2_row_off) * PITCH + kb + b2_col_off);
                ldsm_x2(bh + 4, tBhi + bo2);
                ldsm_x2(bl + 4, tBlo + bo2);
            }
#pragma unroll
            for (int mt = 0; mt < 2; ++mt)
#pragma unroll
                for (int nt = 0; nt < 3; ++nt) {
                    mma_f16(acc[mt][nt], ah[mt], &bh[nt * 2]);
                    mma_f16(acc[mt][nt], ah[mt], &bl[nt * 2]);
                }
        }
        __syncthreads();

        if (c + NSTAGE < NCH) load_chunk(c + NSTAGE, stage_idx);
        CP_COMMIT();
        stage_idx = (stage_idx + 1 == NSTAGE) ? 0 : stage_idx + 1;
    }

    // ---- epilogue: bias + relu ----
    const int col_base = n0 + warp_n * 24 + 2 * (lid & 3);
    const int row_base = m0 + warp_m * 32 + (lid >> 2);
#pragma unroll
    for (int mt = 0; mt < 2; ++mt) {
#pragma unroll
        for (int nt = 0; nt < 3; ++nt) {
            const int col = col_base + nt * 8;
            const float2 bv = *reinterpret_cast<const float2*>(&bias[col]);
#pragma unroll
            for (int h = 0; h < 2; ++h) {
                const int row = row_base + mt * 16 + h * 8;
                float2 o;
                o.x = fmaxf(acc[mt][nt][2 * h + 0] + bv.x, 0.f);
                o.y = fmaxf(acc[mt][nt][2 * h + 1] + bv.y, 0.f);
                *reinterpret_cast<float2*>(&out[(size_t)row * GN + col]) = o;
            }
        }
    }
}

// ---------------------------------------------------------------------------
extern "C" void kernel_launch(void* const* d_in, const int* in_sizes, int n_in,
                              void* d_out, int out_size)
{
    const float* text = (const float*)d_in[0];
    const float* adj  = (const float*)d_in[1];
    const float* dep  = (const float*)d_in[2];
    const float* W    = (const float*)d_in[3];
    const float* bias = (const float*)d_in[4];
    float* out = (float*)d_out;

    __half *Ahi, *Whi, *Wlo;
    cudaGetSymbolAddress((void**)&Ahi, g_Ahi);
    cudaGetSymbolAddress((void**)&Whi, g_Whi);
    cudaGetSymbolAddress((void**)&Wlo, g_Wlo);

    cudaFuncSetAttribute(gemm_hmma, cudaFuncAttributeMaxDynamicSharedMemorySize, GEMM_SMEM);

    prep_kernel<<<AGG_BLOCKS + WSP_BLOCKS, 256>>>(text, adj, dep, W, Ahi, Whi, Wlo);
    gemm_hmma<<<dim3(GN / BN, GM / BM), 256, GEMM_SMEM>>>(Ahi, Whi, Wlo, bias, out);
}

// round 15
// speedup vs baseline: 1.1463x; 1.0254x over previous
#include <cuda_runtime.h>
#include <cuda_fp16.h>
#include <cstdint>

#define BB 8
#define LL 128
#define DD 768
#define TI 4

#define GM (BB * LL)   // 1024
#define GN DD          // 768
#define GK DD          // 768

#define PREP_THREADS 192
#define AGG_BLOCKS (BB * (LL / TI))          // 256
#define WSP_BLOCKS ((GN / 64) * (GK / 64))   // 144

// ---------------- global scratch (no allocation allowed) ----------------
__device__ __half g_Ahi[GM * GK];
__device__ __half g_Whi[GN * GK];   // [n][k]  (W transposed)
__device__ __half g_Wlo[GN * GK];

__device__ __forceinline__ uint32_t pack_h2(float a, float b) {
    __half2 h = __floats2half2_rn(a, b);
    return *reinterpret_cast<uint32_t*>(&h);
}

// ---------------------------------------------------------------------------
// Combined kernel 1 (192 threads): blocks [0,256) agg (float4 path);
// blocks [256,400) W split.
// ---------------------------------------------------------------------------
__global__ void __launch_bounds__(PREP_THREADS, 4)
prep_kernel(const float* __restrict__ text,
            const float* __restrict__ adj,
            const float* __restrict__ dep,
            const float* __restrict__ W,
            __half* __restrict__ Ahi,
            __half* __restrict__ Whi,
            __half* __restrict__ Wlo)
{
    __shared__ float sh[64 * 65];
    const int tid = threadIdx.x;

    if (blockIdx.x < AGG_BLOCKS) {
        // ---------------- agg role: float4 loads ----------------
        const int b  = blockIdx.x / (LL / TI);
        const int i0 = (blockIdx.x % (LL / TI)) * TI;

        float (*s_adj)[LL] = reinterpret_cast<float (*)[LL]>(sh);
        for (int k = tid; k < TI * LL; k += PREP_THREADS) {
            int ii = k / LL, j = k % LL;
            s_adj[ii][j] = adj[((size_t)b * LL + (i0 + ii)) * LL + j];
        }
        __syncthreads();

        float4 acc[TI];
#pragma unroll
        for (int ii = 0; ii < TI; ++ii) acc[ii] = make_float4(0.f, 0.f, 0.f, 0.f);

        const float4* textb = reinterpret_cast<const float4*>(text + (size_t)b * LL * DD);
        const float*  depb  = dep + (size_t)b * LL * LL * DD;
        const int D4 = DD / 4;    // 192

#pragma unroll 2
        for (int j = 0; j < LL; ++j) {
            const float4 t = textb[(size_t)j * D4 + tid];
            const float4* dj = reinterpret_cast<const float4*>(
                depb + (size_t)j * LL * DD + (size_t)i0 * DD) + tid;
#pragma unroll
            for (int ii = 0; ii < TI; ++ii) {
                const float a = s_adj[ii][j];
                const float4 e = dj[ii * D4];
                acc[ii].x = fmaf(a, t.x + e.x, acc[ii].x);
                acc[ii].y = fmaf(a, t.y + e.y, acc[ii].y);
                acc[ii].z = fmaf(a, t.z + e.z, acc[ii].z);
                acc[ii].w = fmaf(a, t.w + e.w, acc[ii].w);
            }
        }

#pragma unroll
        for (int ii = 0; ii < TI; ++ii) {
            uint2 h;
            h.x = pack_h2(acc[ii].x, acc[ii].y);
            h.y = pack_h2(acc[ii].z, acc[ii].w);
            const size_t idx = ((size_t)b * LL + (i0 + ii)) * (size_t)GK + tid * 4;
            *reinterpret_cast<uint2*>(Ahi + idx) = h;
        }
    } else {
        // ---------------- wsplit role (strided loops, 192 threads) ----------
        const int w  = blockIdx.x - AGG_BLOCKS;
        const int n0 = (w % (GN / 64)) * 64;
        const int k0 = (w / (GN / 64)) * 64;
        float (*t)[65] = reinterpret_cast<float (*)[65]>(sh);

        for (int idx = tid; idx < 64 * 16; idx += PREP_THREADS) {
            const int row = idx >> 4;          // local k
            const int c4  = (idx & 15) * 4;    // local n (4 consecutive)
            const float4 v = *reinterpret_cast<const float4*>(
                &W[(size_t)(k0 + row) * GN + n0 + c4]);
            t[row][c4 + 0] = v.x;
            t[row][c4 + 1] = v.y;
            t[row][c4 + 2] = v.z;
            t[row][c4 + 3] = v.w;
        }
        __syncthreads();

        for (int idx = tid; idx < 64 * 16; idx += PREP_THREADS) {
            const int n = idx >> 4;            // local n
            const int k = (idx & 15) * 4;      // local k (4 consecutive)
            const float v0 = t[k + 0][n];
            const float v1 = t[k + 1][n];
            const float v2 = t[k + 2][n];
            const float v3 = t[k + 3][n];
            const float h0 = __half2float(__float2half(v0));
            const float h1 = __half2float(__float2half(v1));
            const float h2 = __half2float(__float2half(v2));
            const float h3 = __half2float(__float2half(v3));
            uint2 hi, lo;
            hi.x = pack_h2(v0, v1);
            hi.y = pack_h2(v2, v3);
            lo.x = pack_h2(v0 - h0, v1 - h1);
            lo.y = pack_h2(v2 - h2, v3 - h3);
            const size_t gidx = (size_t)(n0 + n) * GK + k0 + k;
            *reinterpret_cast<uint2*>(Whi + gidx) = hi;
            *reinterpret_cast<uint2*>(Wlo + gidx) = lo;
        }
    }
}

// ---------------------------------------------------------------------------
// Kernel 2: HMMA fp16 GEMM, 2-pass (Ahi*Whi + Ahi*Wlo), fp32 accum.
// 64x96 CTA tile -> 128 CTAs (one wave), BK=64, 3-stage cp.async ring,
// 8 warps: warp tile 32x24.   (R10-proven, byte-identical)
// ---------------------------------------------------------------------------
#define BM 64
#define BN 96
#define BK 64
#define NCH (GK / BK)            // 12
#define NSTAGE 3
#define PITCH 144
#define A_TILE_B (BM * PITCH)    // 9216
#define B_TILE_B (BN * PITCH)    // 13824
#define STAGE_B (A_TILE_B + 2 * B_TILE_B)   // 36864
#define GEMM_SMEM (NSTAGE * STAGE_B)        // 110592

__device__ __forceinline__ uint32_t smem_u32(const void* p) {
    uint32_t a;
    asm("{ .reg .u64 t; cvta.to.shared.u64 t, %1; cvt.u32.u64 %0, t; }" : "=r"(a) : "l"(p));
    return a;
}
__device__ __forceinline__ void cp_async16(uint32_t dst, const void* src) {
    asm volatile("cp.async.cg.shared.global [%0], [%1], 16;" :: "r"(dst), "l"(src));
}
#define CP_COMMIT() asm volatile("cp.async.commit_group;")
#define CP_WAIT2()  asm volatile("cp.async.wait_group 2;")

__device__ __forceinline__ void ldsm_x4(uint32_t* r, uint32_t addr) {
    asm volatile("ldmatrix.sync.aligned.m8n8.x4.shared.b16 {%0,%1,%2,%3}, [%4];"
                 : "=r"(r[0]), "=r"(r[1]), "=r"(r[2]), "=r"(r[3]) : "r"(addr));
}
__device__ __forceinline__ void ldsm_x2(uint32_t* r, uint32_t addr) {
    asm volatile("ldmatrix.sync.aligned.m8n8.x2.shared.b16 {%0,%1}, [%2];"
                 : "=r"(r[0]), "=r"(r[1]) : "r"(addr));
}
__device__ __forceinline__ void mma_f16(float* c, const uint32_t* a, const uint32_t* b) {
    asm volatile(
        "mma.sync.aligned.m16n8k16.row.col.f32.f16.f16.f32 "
        "{%0,%1,%2,%3}, {%4,%5,%6,%7}, {%8,%9}, {%0,%1,%2,%3};"
        : "+f"(c[0]), "+f"(c[1]), "+f"(c[2]), "+f"(c[3])
        : "r"(a[0]), "r"(a[1]), "r"(a[2]), "r"(a[3]), "r"(b[0]), "r"(b[1]));
}

__global__ void __launch_bounds__(256, 1)
gemm_hmma(const __half* __restrict__ Ahi,
          const __half* __restrict__ Whi,
          const __half* __restrict__ Wlo,
          const float* __restrict__ bias,
          float* __restrict__ out)
{
    extern __shared__ char smem[];
    const uint32_t sbase = smem_u32(smem);
    const int tid = threadIdx.x;
    const int wid = tid >> 5;
    const int lid = tid & 31;

    const int n0 = blockIdx.x * BN;
    const int m0 = blockIdx.y * BM;
    const int warp_m = wid >> 2;     // 0..1
    const int warp_n = wid & 3;      // 0..3

    const int l_row = tid >> 3;      // 0..31
    const int l_c16 = tid & 7;

    float acc[2][3][4];
#pragma unroll
    for (int mt = 0; mt < 2; ++mt)
#pragma unroll
        for (int nt = 0; nt < 3; ++nt)
#pragma unroll
            for (int r = 0; r < 4; ++r) acc[mt][nt][r] = 0.f;

    auto load_chunk = [&](int c, int s) {
        const int k0 = c * BK;
        const uint32_t stage = sbase + s * STAGE_B;
        const uint32_t tAhi = stage;
        const uint32_t tBhi = stage + A_TILE_B;
        const uint32_t tBlo = stage + A_TILE_B + B_TILE_B;
#pragma unroll
        for (int i = 0; i < 2; ++i) {
            const int row = l_row + 32 * i;
            const uint32_t doff = (uint32_t)(row * PITCH + l_c16 * 16);
            const size_t ga = (size_t)(m0 + row) * GK + k0 + l_c16 * 8;
            cp_async16(tAhi + doff, Ahi + ga);
        }
#pragma unroll
        for (int i = 0; i < 3; ++i) {
            const int row = l_row + 32 * i;
            const uint32_t doff = (uint32_t)(row * PITCH + l_c16 * 16);
            const size_t gb = (size_t)(n0 + row) * GK + k0 + l_c16 * 8;
            cp_async16(tBhi + doff, Whi + gb);
            cp_async16(tBlo + doff, Wlo + gb);
        }
    };

    load_chunk(0, 0); CP_COMMIT();
    load_chunk(1, 1); CP_COMMIT();
    load_chunk(2, 2); CP_COMMIT();

    const int a_sub = lid >> 3;
    const int a_row_off = (a_sub & 1) * 8 + (lid & 7);
    const int a_col_off = (a_sub >> 1) * 16;
    const int b_sub = lid >> 3;
    const int b_row_off = (b_sub >> 1) * 8 + (lid & 7);
    const int b_col_off = (b_sub & 1) * 16;
    const int b2_row_off = 16 + (lid & 7);
    const int b2_col_off = ((lid >> 3) & 1) * 16;

    int stage_idx = 0;
    for (int c = 0; c < NCH; ++c) {
        CP_WAIT2();
        __syncthreads();

        const uint32_t stage = sbase + stage_idx * STAGE_B;
        const uint32_t tAhi = stage;
        const uint32_t tBhi = stage + A_TILE_B;
        const uint32_t tBlo = stage + A_TILE_B + B_TILE_B;

#pragma unroll
        for (int ks = 0; ks < BK / 16; ++ks) {
            const int kb = ks * 32;
            uint32_t ah[2][4], bh[6], bl[6];
#pragma unroll
            for (int mt = 0; mt < 2; ++mt) {
                const uint32_t ao =
                    (uint32_t)((warp_m * 32 + mt * 16 + a_row_off) * PITCH + kb + a_col_off);
                ldsm_x4(ah[mt], tAhi + ao);
            }
            {
                const uint32_t bo =
                    (uint32_t)((warp_n * 24 + b_row_off) * PITCH + kb + b_col_off);
                ldsm_x4(bh, tBhi + bo);
                ldsm_x4(bl, tBlo + bo);
                const uint32_t bo2 =
                    (uint32_t)((warp_n * 24 + b2_row_off) * PITCH + kb + b2_col_off);
                ldsm_x2(bh + 4, tBhi + bo2);
                ldsm_x2(bl + 4, tBlo + bo2);
            }
#pragma unroll
            for (int mt = 0; mt < 2; ++mt)
#pragma unroll
                for (int nt = 0; nt < 3; ++nt) {
                    mma_f16(acc[mt][nt], ah[mt], &bh[nt * 2]);
                    mma_f16(acc[mt][nt], ah[mt], &bl[nt * 2]);
                }
        }
        __syncthreads();

        if (c + NSTAGE < NCH) load_chunk(c + NSTAGE, stage_idx);
        CP_COMMIT();
        stage_idx = (stage_idx + 1 == NSTAGE) ? 0 : stage_idx + 1;
    }

    // ---- epilogue: bias + relu ----
    const int col_base = n0 + warp_n * 24 + 2 * (lid & 3);
    const int row_base = m0 + warp_m * 32 + (lid >> 2);
#pragma unroll
    for (int mt = 0; mt < 2; ++mt) {
#pragma unroll
        for (int nt = 0; nt < 3; ++nt) {
            const int col = col_base + nt * 8;
            const float2 bv = *reinterpret_cast<const float2*>(&bias[col]);
#pragma unroll
            for (int h = 0; h < 2; ++h) {
                const int row = row_base + mt * 16 + h * 8;
                float2 o;
                o.x = fmaxf(acc[mt][nt][2 * h + 0] + bv.x, 0.f);
                o.y = fmaxf(acc[mt][nt][2 * h + 1] + bv.y, 0.f);
                *reinterpret_cast<float2*>(&out[(size_t)row * GN + col]) = o;
            }
        }
    }
}

// ---------------------------------------------------------------------------
extern "C" void kernel_launch(void* const* d_in, const int* in_sizes, int n_in,
                              void* d_out, int out_size)
{
    const float* text = (const float*)d_in[0];
    const float* adj  = (const float*)d_in[1];
    const float* dep  = (const float*)d_in[2];
    const float* W    = (const float*)d_in[3];
    const float* bias = (const float*)d_in[4];
    float* out = (float*)d_out;

    __half *Ahi, *Whi, *Wlo;
    cudaGetSymbolAddress((void**)&Ahi, g_Ahi);
    cudaGetSymbolAddress((void**)&Whi, g_Whi);
    cudaGetSymbolAddress((void**)&Wlo, g_Wlo);

    cudaFuncSetAttribute(gemm_hmma, cudaFuncAttributeMaxDynamicSharedMemorySize, GEMM_SMEM);

    prep_kernel<<<AGG_BLOCKS + WSP_BLOCKS, PREP_THREADS>>>(text, adj, dep, W, Ahi, Whi, Wlo);
    gemm_hmma<<<dim3(GN / BN, GM / BM), 256, GEMM_SMEM>>>(Ahi, Whi, Wlo, bias, out);
}